// round 1
// baseline (speedup 1.0000x reference)
#include <cuda_runtime.h>
#include <math.h>

// ---------------------------------------------------------------------------
// SNN: 5-layer LIF net, 25 steps, batch 2048.
// dims: 100 -> 128 -> 256 -> 512 -> 1024 -> 784
// Per step: cur = relu(h @ W^T + b); reset = (mem_old > 1); mem = 0.95*mem_old
//           + cur - reset; spk = (mem > 1). Layer-1 cur is constant across
//           steps (input x fixed) -> computed once.
// Output: [25,2048,784] spikes, then [25,2048,784] tanh(mem5).
// ---------------------------------------------------------------------------

#define BETA_ 0.95f

namespace {
constexpr int BATCH = 2048;
constexpr int TSTEPS = 25;

constexpr int BM = 128, BN = 64, BK = 16;
constexpr int LDA_S = BM + 4;  // 132, pad kills transpose-store bank conflicts
constexpr int LDB_S = BN + 4;  // 68
}

// Persistent scratch (allocation-free rule: __device__ globals).
// mem layout: [128 | 256 | 512 | 1024 | 784] * 2048
__device__ float g_mem[(size_t)BATCH * (128 + 256 + 512 + 1024 + 784)];
// spk layout: [128 | 256 | 512 | 1024] * 2048
__device__ float g_spk[(size_t)BATCH * (128 + 256 + 512 + 1024)];
__device__ float g_cur1[(size_t)BATCH * 128];

__global__ void zero_kernel(float* __restrict__ p, int n) {
    int i = blockIdx.x * blockDim.x + threadIdx.x;
    int stride = gridDim.x * blockDim.x;
    for (; i < n; i += stride) p[i] = 0.0f;
}

// Layer-1 LIF state update (cur1 precomputed, constant over t).
__global__ void lif1_kernel(float* __restrict__ mem, const float* __restrict__ cur,
                            float* __restrict__ spk, int n) {
    int i = blockIdx.x * blockDim.x + threadIdx.x;
    int stride = gridDim.x * blockDim.x;
    for (; i < n; i += stride) {
        float mo = mem[i];
        float reset = (mo > 1.0f) ? 1.0f : 0.0f;
        float mn = fmaf(BETA_, mo, cur[i]) - reset;
        mem[i] = mn;
        spk[i] = (mn > 1.0f) ? 1.0f : 0.0f;
    }
}

// Fused GEMM (+bias, relu) + optional LIF + optional last-layer outputs.
// C[m,n] = sum_k A[m,k] * W[n,k] + bias[n], A: BATCH x K, W: N x K (row major,
// K contiguous in both -> "NT" layout, coalesced float4 loads).
// Tiles: BM=128 x BN=64 x BK=16; 256 threads, 8x4 per-thread microtile.
template <int DO_LIF, int LAST>
__global__ __launch_bounds__(256, 2) void gemm_lif_kernel(
    const float* __restrict__ A, const float* __restrict__ W,
    const float* __restrict__ bias, float* __restrict__ mem,
    float* __restrict__ spk_out, float* __restrict__ out_mem, int N, int K) {
    __shared__ float As[BK * LDA_S];
    __shared__ float Bs[BK * LDB_S];

    const int tid = threadIdx.x;
    const int tx = tid & 15;   // n-dim, 4 cols each -> 64
    const int ty = tid >> 4;   // m-dim, 8 rows each -> 128
    const int bn0 = blockIdx.x * BN;
    const int bm0 = blockIdx.y * BM;

    float acc[8][4];
#pragma unroll
    for (int i = 0; i < 8; i++)
#pragma unroll
        for (int j = 0; j < 4; j++) acc[i][j] = 0.0f;

    const int ktiles = (K + BK - 1) / BK;
    for (int kt = 0; kt < ktiles; kt++) {
        const int k0 = kt * BK;
        // ---- load A tile (128x16) transposed into As[k][m]; 512 float4s ----
#pragma unroll
        for (int r = 0; r < 2; r++) {
            int f = tid + r * 256;
            int m = f >> 2;
            int kq = f & 3;
            int k = k0 + kq * 4;
            float4 v = make_float4(0.f, 0.f, 0.f, 0.f);
            if (k < K)  // K is always a multiple of 4
                v = *reinterpret_cast<const float4*>(A + (size_t)(bm0 + m) * K + k);
            As[(kq * 4 + 0) * LDA_S + m] = v.x;
            As[(kq * 4 + 1) * LDA_S + m] = v.y;
            As[(kq * 4 + 2) * LDA_S + m] = v.z;
            As[(kq * 4 + 3) * LDA_S + m] = v.w;
        }
        // ---- load W tile (64x16) transposed into Bs[k][n]; 256 float4s ----
        {
            int n = tid >> 2;
            int kq = tid & 3;
            int k = k0 + kq * 4;
            int gn = bn0 + n;
            float4 v = make_float4(0.f, 0.f, 0.f, 0.f);
            if (k < K && gn < N)
                v = *reinterpret_cast<const float4*>(W + (size_t)gn * K + k);
            Bs[(kq * 4 + 0) * LDB_S + n] = v.x;
            Bs[(kq * 4 + 1) * LDB_S + n] = v.y;
            Bs[(kq * 4 + 2) * LDB_S + n] = v.z;
            Bs[(kq * 4 + 3) * LDB_S + n] = v.w;
        }
        __syncthreads();

#pragma unroll
        for (int k = 0; k < BK; k++) {
            float a[8], bb[4];
            *reinterpret_cast<float4*>(a) =
                *reinterpret_cast<const float4*>(&As[k * LDA_S + ty * 8]);
            *reinterpret_cast<float4*>(a + 4) =
                *reinterpret_cast<const float4*>(&As[k * LDA_S + ty * 8 + 4]);
            *reinterpret_cast<float4*>(bb) =
                *reinterpret_cast<const float4*>(&Bs[k * LDB_S + tx * 4]);
#pragma unroll
            for (int i = 0; i < 8; i++)
#pragma unroll
                for (int j = 0; j < 4; j++) acc[i][j] = fmaf(a[i], bb[j], acc[i][j]);
        }
        __syncthreads();
    }

    // ---- epilogue: bias + relu (+ LIF + outputs) ----
#pragma unroll
    for (int j = 0; j < 4; j++) {
        int gn = bn0 + tx * 4 + j;
        if (gn >= N) continue;
        float bv = bias[gn];
#pragma unroll
        for (int i = 0; i < 8; i++) {
            int gm = bm0 + ty * 8 + i;
            size_t idx = (size_t)gm * N + gn;
            float cur = fmaxf(acc[i][j] + bv, 0.0f);
            if (DO_LIF) {
                float mo = mem[idx];
                float reset = (mo > 1.0f) ? 1.0f : 0.0f;
                float mn = fmaf(BETA_, mo, cur) - reset;
                mem[idx] = mn;
                float s = (mn > 1.0f) ? 1.0f : 0.0f;
                spk_out[idx] = s;
                if (LAST) out_mem[idx] = tanhf(mn);
            } else {
                spk_out[idx] = cur;
            }
        }
    }
}

extern "C" void kernel_launch(void* const* d_in, const int* in_sizes, int n_in,
                              void* d_out, int out_size) {
    const float* x = (const float*)d_in[0];
    const float* W[5] = {(const float*)d_in[1], (const float*)d_in[3],
                         (const float*)d_in[5], (const float*)d_in[7],
                         (const float*)d_in[9]};
    const float* bb[5] = {(const float*)d_in[2], (const float*)d_in[4],
                          (const float*)d_in[6], (const float*)d_in[8],
                          (const float*)d_in[10]};
    float* out = (float*)d_out;

    float *mem_base = nullptr, *spk_base = nullptr, *cur1 = nullptr;
    cudaGetSymbolAddress((void**)&mem_base, g_mem);
    cudaGetSymbolAddress((void**)&spk_base, g_spk);
    cudaGetSymbolAddress((void**)&cur1, g_cur1);

    // per-layer scratch offsets (in elements)
    float* mem1 = mem_base;
    float* mem2 = mem_base + (size_t)BATCH * 128;
    float* mem3 = mem_base + (size_t)BATCH * (128 + 256);
    float* mem4 = mem_base + (size_t)BATCH * (128 + 256 + 512);
    float* mem5 = mem_base + (size_t)BATCH * (128 + 256 + 512 + 1024);
    float* spk1 = spk_base;
    float* spk2 = spk_base + (size_t)BATCH * 128;
    float* spk3 = spk_base + (size_t)BATCH * (128 + 256);
    float* spk4 = spk_base + (size_t)BATCH * (128 + 256 + 512);

    const int mem_total = BATCH * (128 + 256 + 512 + 1024 + 784);
    zero_kernel<<<1024, 256>>>(mem_base, mem_total);

    // Layer-1 current: constant over timesteps, compute once.
    // M=2048, N=128, K=100
    gemm_lif_kernel<0, 0><<<dim3(2, 16), 256>>>(x, W[0], bb[0], nullptr, cur1,
                                                nullptr, 128, 100);

    const size_t OUT_HALF = (size_t)TSTEPS * BATCH * 784;
    for (int t = 0; t < TSTEPS; t++) {
        lif1_kernel<<<512, 256>>>(mem1, cur1, spk1, BATCH * 128);
        gemm_lif_kernel<1, 0><<<dim3(4, 16), 256>>>(spk1, W[1], bb[1], mem2,
                                                    spk2, nullptr, 256, 128);
        gemm_lif_kernel<1, 0><<<dim3(8, 16), 256>>>(spk2, W[2], bb[2], mem3,
                                                    spk3, nullptr, 512, 256);
        gemm_lif_kernel<1, 0><<<dim3(16, 16), 256>>>(spk3, W[3], bb[3], mem4,
                                                     spk4, nullptr, 1024, 512);
        float* o_spk = out + (size_t)t * BATCH * 784;
        float* o_mem = out + OUT_HALF + (size_t)t * BATCH * 784;
        gemm_lif_kernel<1, 1><<<dim3(13, 16), 256>>>(spk4, W[4], bb[4], mem5,
                                                     o_spk, o_mem, 784, 1024);
    }
}

// round 4
// speedup vs baseline: 1.5312x; 1.5312x over previous
#include <cuda_runtime.h>
#include <cuda_bf16.h>
#include <cstdint>
#include <math.h>

// ---------------------------------------------------------------------------
// SNN 5-layer LIF, 25 steps, batch 2048, dims 100->128->256->512->1024->784.
// Layers 2-5: HMMA bf16 GEMM, 3-way bf16 weight split (exact products, LHS is
// {0,1} spikes). Chunked accumulation: per-k16 temp fragment flushed into a
// master fp32 accumulator via RN FADDs -> avoids tensor-core large-acc
// truncation bias. Layer 1 (dense input, constant over t) fp32 SIMT, once.
// ---------------------------------------------------------------------------

#define BETA_ 0.95f

namespace {
constexpr int BATCH = 2048;
constexpr int TSTEPS = 25;
constexpr int WSZ2 = 256 * 128, WSZ3 = 512 * 256, WSZ4 = 1024 * 512;
constexpr int WSZ5 = 784 * 1024;          // real
constexpr int WSZ5P = 832 * 1024;         // padded to N multiple of 64
constexpr size_t WOFF2 = 0;
constexpr size_t WOFF3 = WOFF2 + 3ull * WSZ2;
constexpr size_t WOFF4 = WOFF3 + 3ull * WSZ3;
constexpr size_t WOFF5 = WOFF4 + 3ull * WSZ4;
constexpr size_t WTOT = WOFF5 + 3ull * WSZ5P;
}  // namespace

// ---- persistent scratch (__device__ globals; no allocs allowed) ----
__device__ __align__(16) float g_mem[(size_t)BATCH * (128 + 256 + 512 + 1024 + 784)];
__device__ __align__(16) __nv_bfloat16 g_spkb[(size_t)BATCH * (128 + 256 + 512 + 1024)];
__device__ __align__(16) float g_cur1[(size_t)BATCH * 128];
__device__ __align__(16) __nv_bfloat16 g_wsplit[WTOT];  // zero-init => L5 pad rows stay 0

// ======================= PTX helpers (arch-neutral) ========================
__device__ __forceinline__ uint32_t smem_u32(const void* p) {
    uint32_t a;
    asm("{ .reg .u64 t; cvta.to.shared.u64 t, %1; cvt.u32.u64 %0, t; }" : "=r"(a) : "l"(p));
    return a;
}
__device__ __forceinline__ void cp_async16(uint32_t dst, const void* src) {
    asm volatile("cp.async.cg.shared.global [%0], [%1], 16;" ::"r"(dst), "l"(src));
}
#define CP_COMMIT() asm volatile("cp.async.commit_group;" ::: "memory")
#define CP_WAIT1() asm volatile("cp.async.wait_group 1;" ::: "memory")
#define CP_WAIT0() asm volatile("cp.async.wait_group 0;" ::: "memory")

__device__ __forceinline__ void ldsm_x4(uint32_t& r0, uint32_t& r1, uint32_t& r2, uint32_t& r3,
                                        uint32_t addr) {
    asm volatile("ldmatrix.sync.aligned.m8n8.x4.shared.b16 {%0,%1,%2,%3}, [%4];"
                 : "=r"(r0), "=r"(r1), "=r"(r2), "=r"(r3)
                 : "r"(addr));
}
__device__ __forceinline__ void mma_bf16(float* c, const uint32_t* a, const uint32_t* b) {
    asm volatile(
        "mma.sync.aligned.m16n8k16.row.col.f32.bf16.bf16.f32 "
        "{%0,%1,%2,%3}, {%4,%5,%6,%7}, {%8,%9}, {%0,%1,%2,%3};"
        : "+f"(c[0]), "+f"(c[1]), "+f"(c[2]), "+f"(c[3])
        : "r"(a[0]), "r"(a[1]), "r"(a[2]), "r"(a[3]), "r"(b[0]), "r"(b[1]));
}

// ======================= small kernels =====================================
__global__ void zero_kernel(float* __restrict__ p, int n) {
    int i = blockIdx.x * blockDim.x + threadIdx.x;
    for (; i < n; i += gridDim.x * blockDim.x) p[i] = 0.0f;
}

// split fp32 weights into 3 bf16 components per layer (L5 padded stride)
__global__ void split_kernel(const float* __restrict__ W2, const float* __restrict__ W3,
                             const float* __restrict__ W4, const float* __restrict__ W5) {
    const int total = WSZ2 + WSZ3 + WSZ4 + WSZ5;
    for (int i = blockIdx.x * blockDim.x + threadIdx.x; i < total;
         i += gridDim.x * blockDim.x) {
        const float* src;
        size_t base;
        int local, stride;
        if (i < WSZ2) { src = W2; base = WOFF2; local = i; stride = WSZ2; }
        else if (i < WSZ2 + WSZ3) { src = W3; base = WOFF3; local = i - WSZ2; stride = WSZ3; }
        else if (i < WSZ2 + WSZ3 + WSZ4) { src = W4; base = WOFF4; local = i - WSZ2 - WSZ3; stride = WSZ4; }
        else { src = W5; base = WOFF5; local = i - WSZ2 - WSZ3 - WSZ4; stride = WSZ5P; }
        float w = src[local];
        __nv_bfloat16 hi = __float2bfloat16(w);
        float r1 = w - __bfloat162float(hi);
        __nv_bfloat16 mid = __float2bfloat16(r1);
        float r2 = r1 - __bfloat162float(mid);
        __nv_bfloat16 lo = __float2bfloat16(r2);
        g_wsplit[base + local] = hi;
        g_wsplit[base + (size_t)stride + local] = mid;
        g_wsplit[base + 2 * (size_t)stride + local] = lo;
    }
}

// layer-1 LIF state update (cur constant over t); spikes as bf16
__global__ void lif1_kernel(float* __restrict__ mem, const float* __restrict__ cur,
                            __nv_bfloat16* __restrict__ spk, int n) {
    int i = blockIdx.x * blockDim.x + threadIdx.x;
    for (; i < n; i += gridDim.x * blockDim.x) {
        float mo = mem[i];
        float reset = (mo > 1.0f) ? 1.0f : 0.0f;
        float mn = fmaf(BETA_, mo, cur[i]) - reset;
        mem[i] = mn;
        spk[i] = __float2bfloat16((mn > 1.0f) ? 1.0f : 0.0f);
    }
}

// ---- fp32 SIMT GEMM for layer 1 (runs once): C = relu(A@W^T + b) ----
namespace {
constexpr int L1BM = 128, L1BN = 64, L1BK = 16;
constexpr int LDA_S = L1BM + 4, LDB_S = L1BN + 4;
}
__global__ __launch_bounds__(256, 2) void gemm_l1(const float* __restrict__ A,
                                                  const float* __restrict__ W,
                                                  const float* __restrict__ bias,
                                                  float* __restrict__ outc, int N, int K) {
    __shared__ float As[L1BK * LDA_S];
    __shared__ float Bs[L1BK * LDB_S];
    const int tid = threadIdx.x;
    const int tx = tid & 15, ty = tid >> 4;
    const int bn0 = blockIdx.x * L1BN, bm0 = blockIdx.y * L1BM;
    float acc[8][4];
#pragma unroll
    for (int i = 0; i < 8; i++)
#pragma unroll
        for (int j = 0; j < 4; j++) acc[i][j] = 0.0f;
    const int ktiles = (K + L1BK - 1) / L1BK;
    for (int kt = 0; kt < ktiles; kt++) {
        const int k0 = kt * L1BK;
#pragma unroll
        for (int r = 0; r < 2; r++) {
            int f = tid + r * 256;
            int m = f >> 2, kq = f & 3, k = k0 + kq * 4;
            float4 v = make_float4(0.f, 0.f, 0.f, 0.f);
            if (k < K) v = *reinterpret_cast<const float4*>(A + (size_t)(bm0 + m) * K + k);
            As[(kq * 4 + 0) * LDA_S + m] = v.x;
            As[(kq * 4 + 1) * LDA_S + m] = v.y;
            As[(kq * 4 + 2) * LDA_S + m] = v.z;
            As[(kq * 4 + 3) * LDA_S + m] = v.w;
        }
        {
            int n = tid >> 2, kq = tid & 3, k = k0 + kq * 4, gn = bn0 + n;
            float4 v = make_float4(0.f, 0.f, 0.f, 0.f);
            if (k < K && gn < N) v = *reinterpret_cast<const float4*>(W + (size_t)gn * K + k);
            Bs[(kq * 4 + 0) * LDB_S + n] = v.x;
            Bs[(kq * 4 + 1) * LDB_S + n] = v.y;
            Bs[(kq * 4 + 2) * LDB_S + n] = v.z;
            Bs[(kq * 4 + 3) * LDB_S + n] = v.w;
        }
        __syncthreads();
#pragma unroll
        for (int k = 0; k < L1BK; k++) {
            float a[8], bb[4];
            *reinterpret_cast<float4*>(a) = *reinterpret_cast<const float4*>(&As[k * LDA_S + ty * 8]);
            *reinterpret_cast<float4*>(a + 4) =
                *reinterpret_cast<const float4*>(&As[k * LDA_S + ty * 8 + 4]);
            *reinterpret_cast<float4*>(bb) = *reinterpret_cast<const float4*>(&Bs[k * LDB_S + tx * 4]);
#pragma unroll
            for (int i = 0; i < 8; i++)
#pragma unroll
                for (int j = 0; j < 4; j++) acc[i][j] = fmaf(a[i], bb[j], acc[i][j]);
        }
        __syncthreads();
    }
#pragma unroll
    for (int j = 0; j < 4; j++) {
        int gn = bn0 + tx * 4 + j;
        if (gn >= N) continue;
        float bv = bias[gn];
#pragma unroll
        for (int i = 0; i < 8; i++) {
            int gm = bm0 + ty * 8 + i;
            outc[(size_t)gm * N + gn] = fmaxf(acc[i][j] + bv, 0.0f);
        }
    }
}

// ================= fused HMMA GEMM + LIF kernel ============================
// A: [2048,K] bf16 spikes. Wsp: 3 stacked [N_PAD,K] bf16 splits.
// CTA tile 128x64, BK=32, 8 warps (2 in M x 4 in N), warp tile 64x16.
// Numerics: per-k16 temp fragment (small acc) flushed into master via RN FADD.
template <int N_REAL, int N_PAD, int K, int LAST>
__global__ __launch_bounds__(256) void hmma_gemm_lif(
    const __nv_bfloat16* __restrict__ A, const __nv_bfloat16* __restrict__ Wsp,
    const float* __restrict__ bias, float* __restrict__ mem,
    __nv_bfloat16* __restrict__ spk_bf, float* __restrict__ out_spk,
    float* __restrict__ out_mem) {
    constexpr int BM = 128, BN = 64, BK = 32;
    constexpr int KT = K / BK;
    constexpr int A_BYTES = BM * BK * 2;           // 8192
    constexpr int B_BYTES = BN * BK * 2;           // 4096 per split
    constexpr int STAGE = A_BYTES + 3 * B_BYTES;   // 20480
    __shared__ __align__(128) char smem[2 * STAGE];

    const int tid = threadIdx.x;
    const int wid = tid >> 5, lane = tid & 31;
    const int wM = wid >> 2, wN = wid & 3;
    const int bn0 = blockIdx.x * BN;
    const int bm0 = blockIdx.y * BM;
    const size_t WSZ = (size_t)N_PAD * K;
    const uint32_t sb = smem_u32(smem);

    float accm[4][2][4];  // master accumulator (RN fp32 adds only)
#pragma unroll
    for (int i = 0; i < 4; i++)
#pragma unroll
        for (int j = 0; j < 2; j++)
#pragma unroll
            for (int q = 0; q < 4; q++) accm[i][j][q] = 0.0f;

    auto issue_stage = [&](int kt, int buf) {
        const int k0 = kt * BK;
        const uint32_t stA = sb + buf * STAGE;
#pragma unroll
        for (int i = 0; i < 2; i++) {
            int f = tid + i * 256;
            int row = f >> 2, c = f & 3;
            const void* src = A + (size_t)(bm0 + row) * K + k0 + c * 8;
            cp_async16(stA + row * 64 + ((c ^ ((row >> 1) & 3)) * 16), src);
        }
#pragma unroll
        for (int s = 0; s < 3; s++) {
            int row = tid >> 2, c = tid & 3;
            const void* src = Wsp + (size_t)s * WSZ + (size_t)(bn0 + row) * K + k0 + c * 8;
            cp_async16(stA + A_BYTES + s * B_BYTES + row * 64 + ((c ^ ((row >> 1) & 3)) * 16),
                       src);
        }
    };

    issue_stage(0, 0);
    CP_COMMIT();
    for (int kt = 0; kt < KT; kt++) {
        if (kt + 1 < KT) {
            issue_stage(kt + 1, (kt + 1) & 1);
            CP_COMMIT();
            CP_WAIT1();
        } else {
            CP_WAIT0();
        }
        __syncthreads();
        const uint32_t sA = sb + (kt & 1) * STAGE;
        const uint32_t sB = sA + A_BYTES;
#pragma unroll
        for (int k16 = 0; k16 < 2; k16++) {
            uint32_t afr[4][4];
#pragma unroll
            for (int mf = 0; mf < 4; mf++) {
                int row = wM * 64 + mf * 16 + (lane & 15);
                int chunk = k16 * 2 + ((lane >> 4) & 1);
                uint32_t addr = sA + row * 64 + ((chunk ^ ((row >> 1) & 3)) * 16);
                ldsm_x4(afr[mf][0], afr[mf][1], afr[mf][2], afr[mf][3], addr);
            }
            // temp fragment starts at zero: tensor-core acc stays small
            float tmp[4][2][4];
#pragma unroll
            for (int i = 0; i < 4; i++)
#pragma unroll
                for (int j = 0; j < 2; j++)
#pragma unroll
                    for (int q = 0; q < 4; q++) tmp[i][j][q] = 0.0f;
#pragma unroll
            for (int s = 0; s < 3; s++) {
                uint32_t bfr[4];
                {
                    int row = wN * 16 + (lane & 7) + ((lane >> 4) & 1) * 8;
                    int chunk = k16 * 2 + ((lane >> 3) & 1);
                    uint32_t addr =
                        sB + s * B_BYTES + row * 64 + ((chunk ^ ((row >> 1) & 3)) * 16);
                    ldsm_x4(bfr[0], bfr[1], bfr[2], bfr[3], addr);
                }
#pragma unroll
                for (int mf = 0; mf < 4; mf++) {
                    mma_bf16(tmp[mf][0], afr[mf], bfr);
                    mma_bf16(tmp[mf][1], afr[mf], bfr + 2);
                }
            }
            // flush chunk into master with IEEE RN fp32 adds
#pragma unroll
            for (int i = 0; i < 4; i++)
#pragma unroll
                for (int j = 0; j < 2; j++)
#pragma unroll
                    for (int q = 0; q < 4; q++) accm[i][j][q] += tmp[i][j][q];
        }
        __syncthreads();
    }

    // ---- epilogue: bias + relu + LIF (+ outputs) ----
    const int tg = lane >> 2;          // row offset within 8
    const int tc = (lane & 3) * 2;     // col offset within 8
#pragma unroll
    for (int mf = 0; mf < 4; mf++) {
#pragma unroll
        for (int nf = 0; nf < 2; nf++) {
            int gn0 = bn0 + wN * 16 + nf * 8 + tc;
            int r0 = bm0 + wM * 64 + mf * 16 + tg;
#pragma unroll
            for (int h = 0; h < 2; h++) {
                int r = r0 + h * 8;
#pragma unroll
                for (int q = 0; q < 2; q++) {
                    int n = gn0 + q;
                    if (N_REAL == N_PAD || n < N_REAL) {
                        float v = accm[mf][nf][h * 2 + q];
                        float cur = fmaxf(v + bias[n], 0.0f);
                        size_t idx = (size_t)r * N_REAL + n;
                        float mo = mem[idx];
                        float reset = (mo > 1.0f) ? 1.0f : 0.0f;
                        float mn = fmaf(BETA_, mo, cur) - reset;
                        mem[idx] = mn;
                        float s = (mn > 1.0f) ? 1.0f : 0.0f;
                        if (LAST) {
                            out_spk[idx] = s;
                            out_mem[idx] = tanhf(mn);
                        } else {
                            spk_bf[idx] = __float2bfloat16(s);
                        }
                    }
                }
            }
        }
    }
}

// ============================= launch ======================================
extern "C" void kernel_launch(void* const* d_in, const int* in_sizes, int n_in,
                              void* d_out, int out_size) {
    const float* x = (const float*)d_in[0];
    const float* W1 = (const float*)d_in[1];
    const float* b1 = (const float*)d_in[2];
    const float* W2 = (const float*)d_in[3];
    const float* b2 = (const float*)d_in[4];
    const float* W3 = (const float*)d_in[5];
    const float* b3 = (const float*)d_in[6];
    const float* W4 = (const float*)d_in[7];
    const float* b4 = (const float*)d_in[8];
    const float* W5 = (const float*)d_in[9];
    const float* b5 = (const float*)d_in[10];
    float* out = (float*)d_out;

    float *mem_base = nullptr, *cur1 = nullptr;
    __nv_bfloat16 *spkb = nullptr, *wsp = nullptr;
    cudaGetSymbolAddress((void**)&mem_base, g_mem);
    cudaGetSymbolAddress((void**)&cur1, g_cur1);
    cudaGetSymbolAddress((void**)&spkb, g_spkb);
    cudaGetSymbolAddress((void**)&wsp, g_wsplit);

    float* mem1 = mem_base;
    float* mem2 = mem_base + (size_t)BATCH * 128;
    float* mem3 = mem_base + (size_t)BATCH * (128 + 256);
    float* mem4 = mem_base + (size_t)BATCH * (128 + 256 + 512);
    float* mem5 = mem_base + (size_t)BATCH * (128 + 256 + 512 + 1024);
    __nv_bfloat16* spk1 = spkb;
    __nv_bfloat16* spk2 = spkb + (size_t)BATCH * 128;
    __nv_bfloat16* spk3 = spkb + (size_t)BATCH * (128 + 256);
    __nv_bfloat16* spk4 = spkb + (size_t)BATCH * (128 + 256 + 512);

    const int mem_total = BATCH * (128 + 256 + 512 + 1024 + 784);
    zero_kernel<<<1024, 256>>>(mem_base, mem_total);
    split_kernel<<<1024, 256>>>(W2, W3, W4, W5);
    // layer-1 current (constant over timesteps): M=2048, N=128, K=100
    gemm_l1<<<dim3(2, 16), 256>>>(x, W1, b1, cur1, 128, 100);

    const size_t OUT_HALF = (size_t)TSTEPS * BATCH * 784;
    for (int t = 0; t < TSTEPS; t++) {
        lif1_kernel<<<512, 256>>>(mem1, cur1, spk1, BATCH * 128);
        hmma_gemm_lif<256, 256, 128, 0><<<dim3(4, 16), 256>>>(
            spk1, wsp + WOFF2, b2, mem2, spk2, nullptr, nullptr);
        hmma_gemm_lif<512, 512, 256, 0><<<dim3(8, 16), 256>>>(
            spk2, wsp + WOFF3, b3, mem3, spk3, nullptr, nullptr);
        hmma_gemm_lif<1024, 1024, 512, 0><<<dim3(16, 16), 256>>>(
            spk3, wsp + WOFF4, b4, mem4, spk4, nullptr, nullptr);
        float* o_spk = out + (size_t)t * BATCH * 784;
        float* o_mem = out + OUT_HALF + (size_t)t * BATCH * 784;
        hmma_gemm_lif<784, 832, 1024, 1><<<dim3(13, 16), 256>>>(
            spk4, wsp + WOFF5, b5, mem5, nullptr, o_spk, o_mem);
    }
}

// round 5
// speedup vs baseline: 2.8616x; 1.8689x over previous
#include <cuda_runtime.h>
#include <cuda_bf16.h>
#include <cstdint>
#include <math.h>

// ---------------------------------------------------------------------------
// SNN 5-layer LIF, 25 steps, batch 2048, dims 100->128->256->512->1024->784.
// Diagonal-wavefront execution: one kernel per wavefront step d runs
// {lif1(d), L2(d-1), L3(d-2), L4(d-3), L5(d-4)} concurrently (independent).
// Spike buffers are parity double-buffered, so concurrent blocks never race.
// GEMMs: HMMA bf16 with 3-way bf16 weight split (exact products, LHS {0,1})
// and chunked accumulation (per-kt temp fragment -> RN FADD master).
// Layer 1 current (constant over t) computed once in fp32 SIMT.
// ---------------------------------------------------------------------------

#define BETA_ 0.95f

namespace {
constexpr int BATCH = 2048;
constexpr int TSTEPS = 25;
constexpr int WSZ2 = 256 * 128, WSZ3 = 512 * 256, WSZ4 = 1024 * 512;
constexpr int WSZ5 = 784 * 1024;   // real
constexpr int WSZ5P = 832 * 1024;  // padded N to multiple of 64
constexpr size_t WOFF2 = 0;
constexpr size_t WOFF3 = WOFF2 + 3ull * WSZ2;
constexpr size_t WOFF4 = WOFF3 + 3ull * WSZ3;
constexpr size_t WOFF5 = WOFF4 + 3ull * WSZ4;
constexpr size_t WTOT = WOFF5 + 3ull * WSZ5P;
constexpr size_t SPK_STRIDE = (size_t)BATCH * (128 + 256 + 512 + 1024);
// block ranges inside the diagonal kernel
constexpr int NB_L2 = 4 * 16;    // 64
constexpr int NB_L3 = 8 * 16;    // 128
constexpr int NB_L4 = 16 * 16;   // 256
constexpr int NB_L5 = 13 * 16;   // 208
constexpr int NB_LIF = 32;
constexpr int NB_TOT = NB_L2 + NB_L3 + NB_L4 + NB_L5 + NB_LIF;  // 688
constexpr int SMEM_DYN = 3 * 20480;  // 3-stage ring
}  // namespace

// ---- persistent scratch (__device__ globals; no allocs allowed) ----
__device__ __align__(16) float g_mem[(size_t)BATCH * (128 + 256 + 512 + 1024 + 784)];
__device__ __align__(16) __nv_bfloat16 g_spkb[2 * SPK_STRIDE];  // parity double buffer
__device__ __align__(16) float g_cur1[(size_t)BATCH * 128];
__device__ __align__(16) __nv_bfloat16 g_wsplit[WTOT];  // zero-init: L5 pad rows stay 0

// ======================= PTX helpers (arch-neutral) ========================
__device__ __forceinline__ uint32_t smem_u32(const void* p) {
    uint32_t a;
    asm("{ .reg .u64 t; cvta.to.shared.u64 t, %1; cvt.u32.u64 %0, t; }" : "=r"(a) : "l"(p));
    return a;
}
__device__ __forceinline__ void cp_async16(uint32_t dst, const void* src) {
    asm volatile("cp.async.cg.shared.global [%0], [%1], 16;" ::"r"(dst), "l"(src));
}
#define CP_COMMIT() asm volatile("cp.async.commit_group;" ::: "memory")
#define CP_WAIT1() asm volatile("cp.async.wait_group 1;" ::: "memory")

__device__ __forceinline__ void ldsm_x4(uint32_t& r0, uint32_t& r1, uint32_t& r2, uint32_t& r3,
                                        uint32_t addr) {
    asm volatile("ldmatrix.sync.aligned.m8n8.x4.shared.b16 {%0,%1,%2,%3}, [%4];"
                 : "=r"(r0), "=r"(r1), "=r"(r2), "=r"(r3)
                 : "r"(addr));
}
__device__ __forceinline__ void mma_bf16(float* c, const uint32_t* a, const uint32_t* b) {
    asm volatile(
        "mma.sync.aligned.m16n8k16.row.col.f32.bf16.bf16.f32 "
        "{%0,%1,%2,%3}, {%4,%5,%6,%7}, {%8,%9}, {%0,%1,%2,%3};"
        : "+f"(c[0]), "+f"(c[1]), "+f"(c[2]), "+f"(c[3])
        : "r"(a[0]), "r"(a[1]), "r"(a[2]), "r"(a[3]), "r"(b[0]), "r"(b[1]));
}

// ======================= setup kernels =====================================
__global__ void zero_kernel(float* __restrict__ p, int n) {
    int i = blockIdx.x * blockDim.x + threadIdx.x;
    for (; i < n; i += gridDim.x * blockDim.x) p[i] = 0.0f;
}

__global__ void split_kernel(const float* __restrict__ W2, const float* __restrict__ W3,
                             const float* __restrict__ W4, const float* __restrict__ W5) {
    const int total = WSZ2 + WSZ3 + WSZ4 + WSZ5;
    for (int i = blockIdx.x * blockDim.x + threadIdx.x; i < total;
         i += gridDim.x * blockDim.x) {
        const float* src;
        size_t base;
        int local, stride;
        if (i < WSZ2) { src = W2; base = WOFF2; local = i; stride = WSZ2; }
        else if (i < WSZ2 + WSZ3) { src = W3; base = WOFF3; local = i - WSZ2; stride = WSZ3; }
        else if (i < WSZ2 + WSZ3 + WSZ4) { src = W4; base = WOFF4; local = i - WSZ2 - WSZ3; stride = WSZ4; }
        else { src = W5; base = WOFF5; local = i - WSZ2 - WSZ3 - WSZ4; stride = WSZ5P; }
        float w = src[local];
        __nv_bfloat16 hi = __float2bfloat16(w);
        float r1 = w - __bfloat162float(hi);
        __nv_bfloat16 mid = __float2bfloat16(r1);
        float r2 = r1 - __bfloat162float(mid);
        __nv_bfloat16 lo = __float2bfloat16(r2);
        g_wsplit[base + local] = hi;
        g_wsplit[base + (size_t)stride + local] = mid;
        g_wsplit[base + 2 * (size_t)stride + local] = lo;
    }
}

// ---- fp32 SIMT GEMM for layer 1 (runs once): C = relu(A@W^T + b) ----
namespace {
constexpr int L1BM = 128, L1BN = 64, L1BK = 16;
constexpr int LDA_S = L1BM + 4, LDB_S = L1BN + 4;
}
__global__ __launch_bounds__(256, 2) void gemm_l1(const float* __restrict__ A,
                                                  const float* __restrict__ W,
                                                  const float* __restrict__ bias,
                                                  float* __restrict__ outc, int N, int K) {
    __shared__ float As[L1BK * LDA_S];
    __shared__ float Bs[L1BK * LDB_S];
    const int tid = threadIdx.x;
    const int tx = tid & 15, ty = tid >> 4;
    const int bn0 = blockIdx.x * L1BN, bm0 = blockIdx.y * L1BM;
    float acc[8][4];
#pragma unroll
    for (int i = 0; i < 8; i++)
#pragma unroll
        for (int j = 0; j < 4; j++) acc[i][j] = 0.0f;
    const int ktiles = (K + L1BK - 1) / L1BK;
    for (int kt = 0; kt < ktiles; kt++) {
        const int k0 = kt * L1BK;
#pragma unroll
        for (int r = 0; r < 2; r++) {
            int f = tid + r * 256;
            int m = f >> 2, kq = f & 3, k = k0 + kq * 4;
            float4 v = make_float4(0.f, 0.f, 0.f, 0.f);
            if (k < K) v = *reinterpret_cast<const float4*>(A + (size_t)(bm0 + m) * K + k);
            As[(kq * 4 + 0) * LDA_S + m] = v.x;
            As[(kq * 4 + 1) * LDA_S + m] = v.y;
            As[(kq * 4 + 2) * LDA_S + m] = v.z;
            As[(kq * 4 + 3) * LDA_S + m] = v.w;
        }
        {
            int n = tid >> 2, kq = tid & 3, k = k0 + kq * 4, gn = bn0 + n;
            float4 v = make_float4(0.f, 0.f, 0.f, 0.f);
            if (k < K && gn < N) v = *reinterpret_cast<const float4*>(W + (size_t)gn * K + k);
            Bs[(kq * 4 + 0) * LDB_S + n] = v.x;
            Bs[(kq * 4 + 1) * LDB_S + n] = v.y;
            Bs[(kq * 4 + 2) * LDB_S + n] = v.z;
            Bs[(kq * 4 + 3) * LDB_S + n] = v.w;
        }
        __syncthreads();
#pragma unroll
        for (int k = 0; k < L1BK; k++) {
            float a[8], bb[4];
            *reinterpret_cast<float4*>(a) = *reinterpret_cast<const float4*>(&As[k * LDA_S + ty * 8]);
            *reinterpret_cast<float4*>(a + 4) =
                *reinterpret_cast<const float4*>(&As[k * LDA_S + ty * 8 + 4]);
            *reinterpret_cast<float4*>(bb) = *reinterpret_cast<const float4*>(&Bs[k * LDB_S + tx * 4]);
#pragma unroll
            for (int i = 0; i < 8; i++)
#pragma unroll
                for (int j = 0; j < 4; j++) acc[i][j] = fmaf(a[i], bb[j], acc[i][j]);
        }
        __syncthreads();
    }
#pragma unroll
    for (int j = 0; j < 4; j++) {
        int gn = bn0 + tx * 4 + j;
        if (gn >= N) continue;
        float bv = bias[gn];
#pragma unroll
        for (int i = 0; i < 8; i++) {
            int gm = bm0 + ty * 8 + i;
            outc[(size_t)gm * N + gn] = fmaxf(acc[i][j] + bv, 0.0f);
        }
    }
}

// ================= per-block fused HMMA GEMM + LIF =========================
// CTA tile 128x64, BK=32, 3-stage cp.async ring, one __syncthreads per kt.
// Numerics: per-kt temp fragment (small acc) flushed into master via RN FADD.
template <int N_REAL, int N_PAD, int K, int LAST>
__device__ __forceinline__ void gemm_block(
    int bn_t, int bm_t, const __nv_bfloat16* __restrict__ A,
    const __nv_bfloat16* __restrict__ Wsp, const float* __restrict__ bias,
    float* __restrict__ mem, __nv_bfloat16* __restrict__ spk_bf,
    float* __restrict__ out_spk, float* __restrict__ out_mem) {
    extern __shared__ __align__(128) char smem[];
    constexpr int BK = 32;
    constexpr int KT = K / BK;
    constexpr int A_BYTES = 8192, B_BYTES = 4096, STAGE = 20480, S = 3;

    const int tid = threadIdx.x;
    const int wid = tid >> 5, lane = tid & 31;
    const int wM = wid >> 2, wN = wid & 3;
    const int bn0 = bn_t * 64, bm0 = bm_t * 128;
    const size_t WSZ = (size_t)N_PAD * K;
    const uint32_t sb = smem_u32(smem);

    auto issue = [&](int kt) {
        const int k0 = kt * BK;
        const uint32_t st = sb + (kt % S) * STAGE;
#pragma unroll
        for (int i = 0; i < 2; i++) {
            int f = tid + i * 256;
            int row = f >> 2, c = f & 3;
            cp_async16(st + row * 64 + ((c ^ ((row >> 1) & 3)) * 16),
                       A + (size_t)(bm0 + row) * K + k0 + c * 8);
        }
#pragma unroll
        for (int s = 0; s < 3; s++) {
            int row = tid >> 2, c = tid & 3;
            cp_async16(st + A_BYTES + s * B_BYTES + row * 64 + ((c ^ ((row >> 1) & 3)) * 16),
                       Wsp + (size_t)s * WSZ + (size_t)(bn0 + row) * K + k0 + c * 8);
        }
    };

    float accm[4][2][4];
#pragma unroll
    for (int i = 0; i < 4; i++)
#pragma unroll
        for (int j = 0; j < 2; j++)
#pragma unroll
            for (int q = 0; q < 4; q++) accm[i][j][q] = 0.0f;

    issue(0);
    CP_COMMIT();
    issue(1);
    CP_COMMIT();
    for (int kt = 0; kt < KT; kt++) {
        CP_WAIT1();           // stage kt resident (groups retire in order)
        __syncthreads();      // all warps done with compute(kt-1) -> slot reusable
        if (kt + 2 < KT) issue(kt + 2);
        CP_COMMIT();          // empty group in tail keeps wait counts uniform
        const uint32_t sA = sb + (kt % S) * STAGE;
        const uint32_t sB = sA + A_BYTES;

        float tmp[4][2][4];   // zeroed per kt: tensor-core acc stays small
#pragma unroll
        for (int i = 0; i < 4; i++)
#pragma unroll
            for (int j = 0; j < 2; j++)
#pragma unroll
                for (int q = 0; q < 4; q++) tmp[i][j][q] = 0.0f;

#pragma unroll
        for (int k16 = 0; k16 < 2; k16++) {
            uint32_t afr[4][4];
#pragma unroll
            for (int mf = 0; mf < 4; mf++) {
                int row = wM * 64 + mf * 16 + (lane & 15);
                int chunk = k16 * 2 + ((lane >> 4) & 1);
                uint32_t addr = sA + row * 64 + ((chunk ^ ((row >> 1) & 3)) * 16);
                ldsm_x4(afr[mf][0], afr[mf][1], afr[mf][2], afr[mf][3], addr);
            }
#pragma unroll
            for (int s = 0; s < 3; s++) {
                uint32_t bfr[4];
                {
                    int row = wN * 16 + (lane & 7) + ((lane >> 4) & 1) * 8;
                    int chunk = k16 * 2 + ((lane >> 3) & 1);
                    uint32_t addr =
                        sB + s * B_BYTES + row * 64 + ((chunk ^ ((row >> 1) & 3)) * 16);
                    ldsm_x4(bfr[0], bfr[1], bfr[2], bfr[3], addr);
                }
#pragma unroll
                for (int mf = 0; mf < 4; mf++) {
                    mma_bf16(tmp[mf][0], afr[mf], bfr);
                    mma_bf16(tmp[mf][1], afr[mf], bfr + 2);
                }
            }
        }
        // flush chunk into master with IEEE RN fp32 adds
#pragma unroll
        for (int i = 0; i < 4; i++)
#pragma unroll
            for (int j = 0; j < 2; j++)
#pragma unroll
                for (int q = 0; q < 4; q++) accm[i][j][q] += tmp[i][j][q];
    }

    // ---- epilogue: bias + relu + LIF (+ outputs) ----
    const int tg = lane >> 2;
    const int tc = (lane & 3) * 2;
#pragma unroll
    for (int mf = 0; mf < 4; mf++) {
#pragma unroll
        for (int nf = 0; nf < 2; nf++) {
            int gn0 = bn0 + wN * 16 + nf * 8 + tc;
            int r0 = bm0 + wM * 64 + mf * 16 + tg;
#pragma unroll
            for (int h = 0; h < 2; h++) {
                int r = r0 + h * 8;
#pragma unroll
                for (int q = 0; q < 2; q++) {
                    int n = gn0 + q;
                    if (N_REAL == N_PAD || n < N_REAL) {
                        float v = accm[mf][nf][h * 2 + q];
                        float cur = fmaxf(v + bias[n], 0.0f);
                        size_t idx = (size_t)r * N_REAL + n;
                        float mo = mem[idx];
                        float reset = (mo > 1.0f) ? 1.0f : 0.0f;
                        float mn = fmaf(BETA_, mo, cur) - reset;
                        mem[idx] = mn;
                        float s = (mn > 1.0f) ? 1.0f : 0.0f;
                        if (LAST) {
                            out_spk[idx] = s;
                            out_mem[idx] = tanhf(mn);
                        } else {
                            spk_bf[idx] = __float2bfloat16(s);
                        }
                    }
                }
            }
        }
    }
}

// ======================= diagonal wavefront kernel =========================
// d: wavefront index. Contains lif1(d), L2(d-1), L3(d-2), L4(d-3), L5(d-4).
__global__ __launch_bounds__(256, 2) void diag_kernel(
    int d, const float* __restrict__ b2, const float* __restrict__ b3,
    const float* __restrict__ b4, const float* __restrict__ b5,
    float* __restrict__ out) {
    const int b = blockIdx.x;
    // scratch base pointers (device globals)
    float* mem1 = g_mem;
    float* mem2 = g_mem + (size_t)BATCH * 128;
    float* mem3 = g_mem + (size_t)BATCH * (128 + 256);
    float* mem4 = g_mem + (size_t)BATCH * (128 + 256 + 512);
    float* mem5 = g_mem + (size_t)BATCH * (128 + 256 + 512 + 1024);

    if (b < NB_L2) {
        const int t = d - 1;
        if (t < 0 || t >= TSTEPS) return;
        const int p = t & 1;
        const __nv_bfloat16* spk1 = g_spkb + (size_t)p * SPK_STRIDE;
        __nv_bfloat16* spk2 = g_spkb + (size_t)p * SPK_STRIDE + (size_t)BATCH * 128;
        gemm_block<256, 256, 128, 0>(b & 3, b >> 2, spk1, g_wsplit + WOFF2, b2, mem2,
                                     spk2, nullptr, nullptr);
    } else if (b < NB_L2 + NB_L3) {
        const int t = d - 2;
        if (t < 0 || t >= TSTEPS) return;
        const int p = t & 1;
        const int idx = b - NB_L2;
        const __nv_bfloat16* spk2 =
            g_spkb + (size_t)p * SPK_STRIDE + (size_t)BATCH * 128;
        __nv_bfloat16* spk3 =
            g_spkb + (size_t)p * SPK_STRIDE + (size_t)BATCH * (128 + 256);
        gemm_block<512, 512, 256, 0>(idx & 7, idx >> 3, spk2, g_wsplit + WOFF3, b3, mem3,
                                     spk3, nullptr, nullptr);
    } else if (b < NB_L2 + NB_L3 + NB_L4) {
        const int t = d - 3;
        if (t < 0 || t >= TSTEPS) return;
        const int p = t & 1;
        const int idx = b - NB_L2 - NB_L3;
        const __nv_bfloat16* spk3 =
            g_spkb + (size_t)p * SPK_STRIDE + (size_t)BATCH * (128 + 256);
        __nv_bfloat16* spk4 =
            g_spkb + (size_t)p * SPK_STRIDE + (size_t)BATCH * (128 + 256 + 512);
        gemm_block<1024, 1024, 512, 0>(idx & 15, idx >> 4, spk3, g_wsplit + WOFF4, b4,
                                       mem4, spk4, nullptr, nullptr);
    } else if (b < NB_L2 + NB_L3 + NB_L4 + NB_L5) {
        const int t = d - 4;
        if (t < 0 || t >= TSTEPS) return;
        const int p = t & 1;
        const int idx = b - NB_L2 - NB_L3 - NB_L4;
        const __nv_bfloat16* spk4 =
            g_spkb + (size_t)p * SPK_STRIDE + (size_t)BATCH * (128 + 256 + 512);
        float* o_spk = out + (size_t)t * BATCH * 784;
        float* o_mem = out + (size_t)TSTEPS * BATCH * 784 + (size_t)t * BATCH * 784;
        gemm_block<784, 832, 1024, 1>(idx % 13, idx / 13, spk4, g_wsplit + WOFF5, b5,
                                      mem5, nullptr, o_spk, o_mem);
    } else {
        // lif1(t = d): mem1/spk1 update from constant cur1
        const int t = d;
        if (t < 0 || t >= TSTEPS) return;
        const int p = t & 1;
        __nv_bfloat16* spk1 = g_spkb + (size_t)p * SPK_STRIDE;
        const int n = BATCH * 128;
        const int lb = b - (NB_L2 + NB_L3 + NB_L4 + NB_L5);
        for (int i = lb * 256 + threadIdx.x; i < n; i += NB_LIF * 256) {
            float mo = mem1[i];
            float reset = (mo > 1.0f) ? 1.0f : 0.0f;
            float mn = fmaf(BETA_, mo, g_cur1[i]) - reset;
            mem1[i] = mn;
            spk1[i] = __float2bfloat16((mn > 1.0f) ? 1.0f : 0.0f);
        }
    }
}

// ============================= launch ======================================
extern "C" void kernel_launch(void* const* d_in, const int* in_sizes, int n_in,
                              void* d_out, int out_size) {
    const float* x = (const float*)d_in[0];
    const float* W1 = (const float*)d_in[1];
    const float* b1 = (const float*)d_in[2];
    const float* W2 = (const float*)d_in[3];
    const float* b2 = (const float*)d_in[4];
    const float* W3 = (const float*)d_in[5];
    const float* b3 = (const float*)d_in[6];
    const float* W4 = (const float*)d_in[7];
    const float* b4 = (const float*)d_in[8];
    const float* W5 = (const float*)d_in[9];
    const float* b5 = (const float*)d_in[10];
    float* out = (float*)d_out;

    float *mem_base = nullptr, *cur1 = nullptr;
    cudaGetSymbolAddress((void**)&mem_base, g_mem);
    cudaGetSymbolAddress((void**)&cur1, g_cur1);

    cudaFuncSetAttribute(diag_kernel, cudaFuncAttributeMaxDynamicSharedMemorySize,
                         SMEM_DYN);

    const int mem_total = BATCH * (128 + 256 + 512 + 1024 + 784);
    zero_kernel<<<1024, 256>>>(mem_base, mem_total);
    split_kernel<<<1024, 256>>>(W2, W3, W4, W5);
    // layer-1 current (constant over timesteps): M=2048, N=128, K=100
    gemm_l1<<<dim3(2, 16), 256>>>(x, W1, b1, cur1, 128, 100);

    // wavefront: d = 0 .. TSTEPS+3  (lif1 at d, L5 at d-4)
    for (int d = 0; d <= TSTEPS + 3; d++) {
        diag_kernel<<<NB_TOT, 256, SMEM_DYN>>>(d, b2, b3, b4, b5, out);
    }
}

// round 7
// speedup vs baseline: 3.1603x; 1.1044x over previous
#include <cuda_runtime.h>
#include <cuda_bf16.h>
#include <cstdint>
#include <math.h>

// ---------------------------------------------------------------------------
// SNN 5-layer LIF, 25 steps, batch 2048, dims 100->128->256->512->1024->784.
// Diagonal-wavefront execution; parity double-buffered spikes; HMMA bf16 with
// 3-way split weights everywhere (2-way empirically flips spikes: ~1e8
// threshold evaluations make even 1e-4 perturbations cascade) and chunked
// accumulation. Long L5 blocks scheduled first in each diagonal.
// ---------------------------------------------------------------------------

#define BETA_ 0.95f

namespace {
constexpr int BATCH = 2048;
constexpr int TSTEPS = 25;
constexpr int WSZ2 = 256 * 128, WSZ3 = 512 * 256, WSZ4 = 1024 * 512;
constexpr int WSZ5 = 784 * 1024;   // real
constexpr int WSZ5P = 832 * 1024;  // padded N to multiple of 64
constexpr size_t WOFF2 = 0;
constexpr size_t WOFF3 = WOFF2 + 3ull * WSZ2;
constexpr size_t WOFF4 = WOFF3 + 3ull * WSZ3;
constexpr size_t WOFF5 = WOFF4 + 3ull * WSZ4;
constexpr size_t WTOT = WOFF5 + 3ull * WSZ5P;
constexpr size_t SPK_STRIDE = (size_t)BATCH * (128 + 256 + 512 + 1024);
// block ranges inside the diagonal kernel (longest first!)
constexpr int NB_L5 = 13 * 16;   // 208  K=1024
constexpr int NB_L4 = 16 * 16;   // 256  K=512
constexpr int NB_L3 = 8 * 16;    // 128  K=256
constexpr int NB_L2 = 4 * 16;    // 64   K=128
constexpr int NB_LIF = 32;
constexpr int NB_TOT = NB_L5 + NB_L4 + NB_L3 + NB_L2 + NB_LIF;  // 688
constexpr int SMEM_DYN = 3 * 20480;  // stage (A 8K + 3x4K) x 3 ring
}  // namespace

// ---- persistent scratch (__device__ globals; no allocs allowed) ----
__device__ __align__(16) float g_mem[(size_t)BATCH * (128 + 256 + 512 + 1024 + 784)];
__device__ __align__(16) __nv_bfloat16 g_spkb[2 * SPK_STRIDE];  // parity double buffer
__device__ __align__(16) float g_cur1[(size_t)BATCH * 128];
__device__ __align__(16) __nv_bfloat16 g_wsplit[WTOT];  // zero-init: L5 pad rows stay 0

// ======================= PTX helpers (arch-neutral) ========================
__device__ __forceinline__ uint32_t smem_u32(const void* p) {
    uint32_t a;
    asm("{ .reg .u64 t; cvta.to.shared.u64 t, %1; cvt.u32.u64 %0, t; }" : "=r"(a) : "l"(p));
    return a;
}
__device__ __forceinline__ void cp_async16(uint32_t dst, const void* src) {
    asm volatile("cp.async.cg.shared.global [%0], [%1], 16;" ::"r"(dst), "l"(src));
}
#define CP_COMMIT() asm volatile("cp.async.commit_group;" ::: "memory")
#define CP_WAIT1() asm volatile("cp.async.wait_group 1;" ::: "memory")

__device__ __forceinline__ void ldsm_x4(uint32_t& r0, uint32_t& r1, uint32_t& r2, uint32_t& r3,
                                        uint32_t addr) {
    asm volatile("ldmatrix.sync.aligned.m8n8.x4.shared.b16 {%0,%1,%2,%3}, [%4];"
                 : "=r"(r0), "=r"(r1), "=r"(r2), "=r"(r3)
                 : "r"(addr));
}
__device__ __forceinline__ void mma_bf16(float* c, const uint32_t* a, const uint32_t* b) {
    asm volatile(
        "mma.sync.aligned.m16n8k16.row.col.f32.bf16.bf16.f32 "
        "{%0,%1,%2,%3}, {%4,%5,%6,%7}, {%8,%9}, {%0,%1,%2,%3};"
        : "+f"(c[0]), "+f"(c[1]), "+f"(c[2]), "+f"(c[3])
        : "r"(a[0]), "r"(a[1]), "r"(a[2]), "r"(a[3]), "r"(b[0]), "r"(b[1]));
}

// ======================= setup kernels =====================================
__global__ void zero_kernel(float* __restrict__ p, int n) {
    int i = blockIdx.x * blockDim.x + threadIdx.x;
    for (; i < n; i += gridDim.x * blockDim.x) p[i] = 0.0f;
}

// 3-way split for all layers
__global__ void split_kernel(const float* __restrict__ W2, const float* __restrict__ W3,
                             const float* __restrict__ W4, const float* __restrict__ W5) {
    const int total = WSZ2 + WSZ3 + WSZ4 + WSZ5;
    for (int i = blockIdx.x * blockDim.x + threadIdx.x; i < total;
         i += gridDim.x * blockDim.x) {
        const float* src;
        size_t base;
        int local, stride;
        if (i < WSZ2) { src = W2; base = WOFF2; local = i; stride = WSZ2; }
        else if (i < WSZ2 + WSZ3) { src = W3; base = WOFF3; local = i - WSZ2; stride = WSZ3; }
        else if (i < WSZ2 + WSZ3 + WSZ4) { src = W4; base = WOFF4; local = i - WSZ2 - WSZ3; stride = WSZ4; }
        else { src = W5; base = WOFF5; local = i - WSZ2 - WSZ3 - WSZ4; stride = WSZ5P; }
        float w = src[local];
        __nv_bfloat16 hi = __float2bfloat16(w);
        float r1 = w - __bfloat162float(hi);
        __nv_bfloat16 mid = __float2bfloat16(r1);
        float r2 = r1 - __bfloat162float(mid);
        g_wsplit[base + local] = hi;
        g_wsplit[base + (size_t)stride + local] = mid;
        g_wsplit[base + 2 * (size_t)stride + local] = __float2bfloat16(r2);
    }
}

// ---- fp32 SIMT GEMM for layer 1 (runs once): C = relu(A@W^T + b) ----
namespace {
constexpr int L1BM = 128, L1BN = 64, L1BK = 16;
constexpr int LDA_S = L1BM + 4, LDB_S = L1BN + 4;
}
__global__ __launch_bounds__(256, 2) void gemm_l1(const float* __restrict__ A,
                                                  const float* __restrict__ W,
                                                  const float* __restrict__ bias,
                                                  float* __restrict__ outc, int N, int K) {
    __shared__ float As[L1BK * LDA_S];
    __shared__ float Bs[L1BK * LDB_S];
    const int tid = threadIdx.x;
    const int tx = tid & 15, ty = tid >> 4;
    const int bn0 = blockIdx.x * L1BN, bm0 = blockIdx.y * L1BM;
    float acc[8][4];
#pragma unroll
    for (int i = 0; i < 8; i++)
#pragma unroll
        for (int j = 0; j < 4; j++) acc[i][j] = 0.0f;
    const int ktiles = (K + L1BK - 1) / L1BK;
    for (int kt = 0; kt < ktiles; kt++) {
        const int k0 = kt * L1BK;
#pragma unroll
        for (int r = 0; r < 2; r++) {
            int f = tid + r * 256;
            int m = f >> 2, kq = f & 3, k = k0 + kq * 4;
            float4 v = make_float4(0.f, 0.f, 0.f, 0.f);
            if (k < K) v = *reinterpret_cast<const float4*>(A + (size_t)(bm0 + m) * K + k);
            As[(kq * 4 + 0) * LDA_S + m] = v.x;
            As[(kq * 4 + 1) * LDA_S + m] = v.y;
            As[(kq * 4 + 2) * LDA_S + m] = v.z;
            As[(kq * 4 + 3) * LDA_S + m] = v.w;
        }
        {
            int n = tid >> 2, kq = tid & 3, k = k0 + kq * 4, gn = bn0 + n;
            float4 v = make_float4(0.f, 0.f, 0.f, 0.f);
            if (k < K && gn < N) v = *reinterpret_cast<const float4*>(W + (size_t)gn * K + k);
            Bs[(kq * 4 + 0) * LDB_S + n] = v.x;
            Bs[(kq * 4 + 1) * LDB_S + n] = v.y;
            Bs[(kq * 4 + 2) * LDB_S + n] = v.z;
            Bs[(kq * 4 + 3) * LDB_S + n] = v.w;
        }
        __syncthreads();
#pragma unroll
        for (int k = 0; k < L1BK; k++) {
            float a[8], bb[4];
            *reinterpret_cast<float4*>(a) = *reinterpret_cast<const float4*>(&As[k * LDA_S + ty * 8]);
            *reinterpret_cast<float4*>(a + 4) =
                *reinterpret_cast<const float4*>(&As[k * LDA_S + ty * 8 + 4]);
            *reinterpret_cast<float4*>(bb) = *reinterpret_cast<const float4*>(&Bs[k * LDB_S + tx * 4]);
#pragma unroll
            for (int i = 0; i < 8; i++)
#pragma unroll
                for (int j = 0; j < 4; j++) acc[i][j] = fmaf(a[i], bb[j], acc[i][j]);
        }
        __syncthreads();
    }
#pragma unroll
    for (int j = 0; j < 4; j++) {
        int gn = bn0 + tx * 4 + j;
        if (gn >= N) continue;
        float bv = bias[gn];
#pragma unroll
        for (int i = 0; i < 8; i++) {
            int gm = bm0 + ty * 8 + i;
            outc[(size_t)gm * N + gn] = fmaxf(acc[i][j] + bv, 0.0f);
        }
    }
}

// ================= per-block fused HMMA GEMM + LIF =========================
// CTA tile 128x64, BK=32, 3-stage cp.async ring, one __syncthreads per kt.
// Numerics: per-kt temp fragment (small acc) flushed into master via RN FADD.
template <int N_REAL, int N_PAD, int K, int LAST>
__device__ __forceinline__ void gemm_block(
    int bn_t, int bm_t, const __nv_bfloat16* __restrict__ A,
    const __nv_bfloat16* __restrict__ Wsp, const float* __restrict__ bias,
    float* __restrict__ mem, __nv_bfloat16* __restrict__ spk_bf,
    float* __restrict__ out_spk, float* __restrict__ out_mem) {
    extern __shared__ __align__(128) char smem[];
    constexpr int BK = 32;
    constexpr int KT = K / BK;
    constexpr int A_BYTES = 8192, B_BYTES = 4096, STAGE = 20480, S = 3;

    const int tid = threadIdx.x;
    const int wid = tid >> 5, lane = tid & 31;
    const int wM = wid >> 2, wN = wid & 3;
    const int bn0 = bn_t * 64, bm0 = bm_t * 128;
    const size_t WSZ = (size_t)N_PAD * K;
    const uint32_t sb = smem_u32(smem);

    auto issue = [&](int kt) {
        const int k0 = kt * BK;
        const uint32_t st = sb + (kt % S) * STAGE;
#pragma unroll
        for (int i = 0; i < 2; i++) {
            int f = tid + i * 256;
            int row = f >> 2, c = f & 3;
            cp_async16(st + row * 64 + ((c ^ ((row >> 1) & 3)) * 16),
                       A + (size_t)(bm0 + row) * K + k0 + c * 8);
        }
#pragma unroll
        for (int s = 0; s < 3; s++) {
            int row = tid >> 2, c = tid & 3;
            cp_async16(st + A_BYTES + s * B_BYTES + row * 64 + ((c ^ ((row >> 1) & 3)) * 16),
                       Wsp + (size_t)s * WSZ + (size_t)(bn0 + row) * K + k0 + c * 8);
        }
    };

    float accm[4][2][4];
#pragma unroll
    for (int i = 0; i < 4; i++)
#pragma unroll
        for (int j = 0; j < 2; j++)
#pragma unroll
            for (int q = 0; q < 4; q++) accm[i][j][q] = 0.0f;

    issue(0);
    CP_COMMIT();
    issue(1);
    CP_COMMIT();
    for (int kt = 0; kt < KT; kt++) {
        CP_WAIT1();           // stage kt resident (groups retire in order)
        __syncthreads();      // all warps done with compute(kt-1) -> slot reusable
        if (kt + 2 < KT) issue(kt + 2);
        CP_COMMIT();          // empty group in tail keeps wait counts uniform
        const uint32_t sA = sb + (kt % S) * STAGE;
        const uint32_t sB = sA + A_BYTES;

        float tmp[4][2][4];   // zeroed per kt: tensor-core acc stays small
#pragma unroll
        for (int i = 0; i < 4; i++)
#pragma unroll
            for (int j = 0; j < 2; j++)
#pragma unroll
                for (int q = 0; q < 4; q++) tmp[i][j][q] = 0.0f;

#pragma unroll
        for (int k16 = 0; k16 < 2; k16++) {
            uint32_t afr[4][4];
#pragma unroll
            for (int mf = 0; mf < 4; mf++) {
                int row = wM * 64 + mf * 16 + (lane & 15);
                int chunk = k16 * 2 + ((lane >> 4) & 1);
                uint32_t addr = sA + row * 64 + ((chunk ^ ((row >> 1) & 3)) * 16);
                ldsm_x4(afr[mf][0], afr[mf][1], afr[mf][2], afr[mf][3], addr);
            }
#pragma unroll
            for (int s = 0; s < 3; s++) {
                uint32_t bfr[4];
                {
                    int row = wN * 16 + (lane & 7) + ((lane >> 4) & 1) * 8;
                    int chunk = k16 * 2 + ((lane >> 3) & 1);
                    uint32_t addr =
                        sB + s * B_BYTES + row * 64 + ((chunk ^ ((row >> 1) & 3)) * 16);
                    ldsm_x4(bfr[0], bfr[1], bfr[2], bfr[3], addr);
                }
#pragma unroll
                for (int mf = 0; mf < 4; mf++) {
                    mma_bf16(tmp[mf][0], afr[mf], bfr);
                    mma_bf16(tmp[mf][1], afr[mf], bfr + 2);
                }
            }
        }
        // flush chunk into master with IEEE RN fp32 adds
#pragma unroll
        for (int i = 0; i < 4; i++)
#pragma unroll
            for (int j = 0; j < 2; j++)
#pragma unroll
                for (int q = 0; q < 4; q++) accm[i][j][q] += tmp[i][j][q];
    }

    // ---- epilogue: bias + relu + LIF (+ outputs) ----
    const int tg = lane >> 2;
    const int tc = (lane & 3) * 2;
#pragma unroll
    for (int mf = 0; mf < 4; mf++) {
#pragma unroll
        for (int nf = 0; nf < 2; nf++) {
            int gn0 = bn0 + wN * 16 + nf * 8 + tc;
            int r0 = bm0 + wM * 64 + mf * 16 + tg;
#pragma unroll
            for (int h = 0; h < 2; h++) {
                int r = r0 + h * 8;
#pragma unroll
                for (int q = 0; q < 2; q++) {
                    int n = gn0 + q;
                    if (N_REAL == N_PAD || n < N_REAL) {
                        float v = accm[mf][nf][h * 2 + q];
                        float cur = fmaxf(v + bias[n], 0.0f);
                        size_t idx = (size_t)r * N_REAL + n;
                        float mo = mem[idx];
                        float reset = (mo > 1.0f) ? 1.0f : 0.0f;
                        float mn = fmaf(BETA_, mo, cur) - reset;
                        mem[idx] = mn;
                        float s = (mn > 1.0f) ? 1.0f : 0.0f;
                        if (LAST) {
                            out_spk[idx] = s;
                            out_mem[idx] = tanhf(mn);
                        } else {
                            spk_bf[idx] = __float2bfloat16(s);
                        }
                    }
                }
            }
        }
    }
}

// ======================= diagonal wavefront kernel =========================
// d: wavefront index. Contains L5(d-4), L4(d-3), L3(d-2), L2(d-1), lif1(d).
// Longest blocks (L5) get the lowest block ids -> scheduled in wave 1.
__global__ __launch_bounds__(256, 2) void diag_kernel(
    int d, const float* __restrict__ b2, const float* __restrict__ b3,
    const float* __restrict__ b4, const float* __restrict__ b5,
    float* __restrict__ out) {
    const int b = blockIdx.x;
    float* mem1 = g_mem;
    float* mem2 = g_mem + (size_t)BATCH * 128;
    float* mem3 = g_mem + (size_t)BATCH * (128 + 256);
    float* mem4 = g_mem + (size_t)BATCH * (128 + 256 + 512);
    float* mem5 = g_mem + (size_t)BATCH * (128 + 256 + 512 + 1024);

    if (b < NB_L5) {
        const int t = d - 4;
        if (t < 0 || t >= TSTEPS) return;
        const int p = t & 1;
        const __nv_bfloat16* spk4 =
            g_spkb + (size_t)p * SPK_STRIDE + (size_t)BATCH * (128 + 256 + 512);
        float* o_spk = out + (size_t)t * BATCH * 784;
        float* o_mem = out + (size_t)TSTEPS * BATCH * 784 + (size_t)t * BATCH * 784;
        gemm_block<784, 832, 1024, 1>(b % 13, b / 13, spk4, g_wsplit + WOFF5, b5,
                                      mem5, nullptr, o_spk, o_mem);
    } else if (b < NB_L5 + NB_L4) {
        const int t = d - 3;
        if (t < 0 || t >= TSTEPS) return;
        const int p = t & 1;
        const int idx = b - NB_L5;
        const __nv_bfloat16* spk3 =
            g_spkb + (size_t)p * SPK_STRIDE + (size_t)BATCH * (128 + 256);
        __nv_bfloat16* spk4 =
            g_spkb + (size_t)p * SPK_STRIDE + (size_t)BATCH * (128 + 256 + 512);
        gemm_block<1024, 1024, 512, 0>(idx & 15, idx >> 4, spk3, g_wsplit + WOFF4, b4,
                                       mem4, spk4, nullptr, nullptr);
    } else if (b < NB_L5 + NB_L4 + NB_L3) {
        const int t = d - 2;
        if (t < 0 || t >= TSTEPS) return;
        const int p = t & 1;
        const int idx = b - NB_L5 - NB_L4;
        const __nv_bfloat16* spk2 =
            g_spkb + (size_t)p * SPK_STRIDE + (size_t)BATCH * 128;
        __nv_bfloat16* spk3 =
            g_spkb + (size_t)p * SPK_STRIDE + (size_t)BATCH * (128 + 256);
        gemm_block<512, 512, 256, 0>(idx & 7, idx >> 3, spk2, g_wsplit + WOFF3, b3,
                                     mem3, spk3, nullptr, nullptr);
    } else if (b < NB_L5 + NB_L4 + NB_L3 + NB_L2) {
        const int t = d - 1;
        if (t < 0 || t >= TSTEPS) return;
        const int p = t & 1;
        const int idx = b - NB_L5 - NB_L4 - NB_L3;
        const __nv_bfloat16* spk1 = g_spkb + (size_t)p * SPK_STRIDE;
        __nv_bfloat16* spk2 = g_spkb + (size_t)p * SPK_STRIDE + (size_t)BATCH * 128;
        gemm_block<256, 256, 128, 0>(idx & 3, idx >> 2, spk1, g_wsplit + WOFF2, b2,
                                     mem2, spk2, nullptr, nullptr);
    } else {
        // lif1(t = d): mem1/spk1 update from constant cur1
        const int t = d;
        if (t < 0 || t >= TSTEPS) return;
        const int p = t & 1;
        __nv_bfloat16* spk1 = g_spkb + (size_t)p * SPK_STRIDE;
        const int n = BATCH * 128;
        const int lb = b - (NB_L5 + NB_L4 + NB_L3 + NB_L2);
        for (int i = lb * 256 + threadIdx.x; i < n; i += NB_LIF * 256) {
            float mo = mem1[i];
            float reset = (mo > 1.0f) ? 1.0f : 0.0f;
            float mn = fmaf(BETA_, mo, g_cur1[i]) - reset;
            mem1[i] = mn;
            spk1[i] = __float2bfloat16((mn > 1.0f) ? 1.0f : 0.0f);
        }
    }
}

// ============================= launch ======================================
extern "C" void kernel_launch(void* const* d_in, const int* in_sizes, int n_in,
                              void* d_out, int out_size) {
    const float* x = (const float*)d_in[0];
    const float* W1 = (const float*)d_in[1];
    const float* b1 = (const float*)d_in[2];
    const float* W2 = (const float*)d_in[3];
    const float* b2 = (const float*)d_in[4];
    const float* W3 = (const float*)d_in[5];
    const float* b3 = (const float*)d_in[6];
    const float* W4 = (const float*)d_in[7];
    const float* b4 = (const float*)d_in[8];
    const float* W5 = (const float*)d_in[9];
    const float* b5 = (const float*)d_in[10];
    float* out = (float*)d_out;

    float *mem_base = nullptr, *cur1 = nullptr;
    cudaGetSymbolAddress((void**)&mem_base, g_mem);
    cudaGetSymbolAddress((void**)&cur1, g_cur1);

    cudaFuncSetAttribute(diag_kernel, cudaFuncAttributeMaxDynamicSharedMemorySize,
                         SMEM_DYN);

    const int mem_total = BATCH * (128 + 256 + 512 + 1024 + 784);
    zero_kernel<<<1024, 256>>>(mem_base, mem_total);
    split_kernel<<<1024, 256>>>(W2, W3, W4, W5);
    // layer-1 current (constant over timesteps): M=2048, N=128, K=100
    gemm_l1<<<dim3(2, 16), 256>>>(x, W1, b1, cur1, 128, 100);

    // wavefront: d = 0 .. TSTEPS+3  (lif1 at d, L5 at d-4)
    for (int d = 0; d <= TSTEPS + 3; d++) {
        diag_kernel<<<NB_TOT, 256, SMEM_DYN>>>(d, b2, b3, b4, b5, out);
    }
}